// round 7
// baseline (speedup 1.0000x reference)
#include <cuda_runtime.h>
#include <math.h>

#define Pp 8
#define RCn 8
#define FCn 768
#define Bb 8
#define HW 4096

typedef unsigned long long ull;

// ---------------- scratch (device globals; no allocation) ----------------
__device__ float g_kern[Pp*81];
__device__ float g_c1[Bb*RCn*HW];
__device__ float g_carrier[Bb*RCn*HW];
__device__ float g_densraw[Bb*HW];
__device__ float g_hp[Bb*HW];
__device__ float g_asup[Bb*HW];
__device__ float g_part[Bb*32*5];
__device__ float g_h[RCn*Bb*HW];

__device__ __forceinline__ float geluf(float x){ return 0.5f*x*(1.0f+erff(x*0.70710678118654752f)); }
__device__ __forceinline__ float sigmf(float x){ return 1.0f/(1.0f+expf(-x)); }

// packed f32x2 helpers (bit-exact per-lane fma/add)
__device__ __forceinline__ ull pk2(float lo, float hi){
    ull r; asm("mov.b64 %0, {%1,%2};" : "=l"(r) : "f"(lo), "f"(hi)); return r;
}
__device__ __forceinline__ void fma2(ull &d, ull a, ull b){
    asm("fma.rn.f32x2 %0, %1, %2, %0;" : "+l"(d) : "l"(a), "l"(b));
}
__device__ __forceinline__ void add2(ull &d, ull a){
    asm("add.rn.f32x2 %0, %0, %1;" : "+l"(d) : "l"(a));
}
__device__ __forceinline__ void up2(ull v, float &lo, float &hi){
    asm("mov.b64 {%0,%1}, %2;" : "=f"(lo), "=f"(hi) : "l"(v));
}

// =====================================================================
// k_conv1: 1x1 conv 768->8 + gelu, f32x2 packed. 512 blocks x 256 thr.
// 16-way channel split (48 ch each), 64 px/block (16 float4 groups).
// Blocks 0..7 additionally build the filter bank.
// =====================================================================
__global__ void k_conv1(const float* __restrict__ fm,
                        const float* __restrict__ w,
                        const float* __restrict__ bias,
                        const float* __restrict__ pd){
    __shared__ float sw[FCn*RCn];           // [c][o] 24KB
    __shared__ ull s_part[15*16*RCn*2];     // packed partials, 30KB
    __shared__ float s_red[256];
    int tid = threadIdx.x;                  // 256
    for(int idx = tid; idx < FCn*RCn; idx += 256){
        int o = idx / FCn, c = idx % FCn;
        sw[c*RCn + o] = w[idx];
    }
    __syncthreads();
    int lane = tid & 15;
    int sp   = tid >> 4;                    // 0..15
    int g4 = blockIdx.x*16 + lane;
    int b = g4 >> 10;
    int pix = (g4 << 2) & 4095;
    const float* xp = fm + ((size_t)b*FCn + sp*48)*HW + pix;
    ull acc2[RCn][2];
    #pragma unroll
    for(int o=0;o<RCn;o++){ acc2[o][0]=0ULL; acc2[o][1]=0ULL; }
    #pragma unroll 4
    for(int c=0;c<48;c++){
        float4 xv = __ldg((const float4*)(xp + (size_t)c*HW));
        ull ax = pk2(xv.x, xv.y), az = pk2(xv.z, xv.w);
        const float* wr = &sw[(sp*48 + c)*RCn];
        #pragma unroll
        for(int o=0;o<RCn;o++){
            float wv = wr[o];
            ull w2 = pk2(wv, wv);
            fma2(acc2[o][0], ax, w2);
            fma2(acc2[o][1], az, w2);
        }
    }
    if (sp > 0){
        ull* dst = &s_part[(((sp-1)*16 + lane)*RCn)*2];
        #pragma unroll
        for(int o=0;o<RCn;o++){ dst[o*2]=acc2[o][0]; dst[o*2+1]=acc2[o][1]; }
    }
    __syncthreads();
    if (sp == 0){
        #pragma unroll
        for(int o=0;o<RCn;o++){
            ull a0=acc2[o][0], a1=acc2[o][1];
            #pragma unroll
            for(int q=0;q<15;q++){
                const ull* src = &s_part[((q*16 + lane)*RCn)*2];
                add2(a0, src[o*2]); add2(a1, src[o*2+1]);
            }
            float bo = bias[o];
            float v0,v1,v2,v3;
            up2(a0,v0,v1); up2(a1,v2,v3);
            float4 r;
            r.x = geluf(v0+bo); r.y = geluf(v1+bo);
            r.z = geluf(v2+bo); r.w = geluf(v3+bo);
            *(float4*)&g_c1[((b*RCn+o)<<12) + pix] = r;
        }
    }
    // ---- filter bank (blocks 0..7) ----
    if (blockIdx.x < 8){
        int i = blockIdx.x;
        float ridge = 0.f;
        if (tid < 81){
            int r = tid/9, c = tid%9;
            float y = -1.0f + 0.25f*(float)r;
            float x = -1.0f + 0.25f*(float)c;
            double angd = 6.283185307179586476925286766559 * (double)i / 8.0;
            const float Ls[3] = {0.45f,0.75f,1.05f};
            const float Ws[3] = {0.14f,0.2f,0.28f};
            float L = Ls[i%3], Wd = Ws[(i/3)%3];
            float ca = (float)cos(angd), sa = (float)sin(angd);
            float xr =  x*ca + y*sa;
            float yr = -x*sa + y*ca;
            float tpr = 1.0f - fminf(fabsf(xr)/L, 1.0f);
            tpr = tpr*sqrtf(tpr);
            float ax = xr/L, ay = yr/Wd;
            float core = expf(-0.5f*(ax*ax + ay*ay));
            float lobe = fmaxf(1.0f - ay*ay, 0.0f);
            ridge = tpr*core*lobe;
        }
        __syncthreads();
        s_red[tid] = (tid<81)? ridge : 0.f;
        __syncthreads();
        for(int s=128;s>0;s>>=1){ if(tid<s) s_red[tid]+=s_red[tid+s]; __syncthreads(); }
        float mean = s_red[0]/81.0f;
        __syncthreads();
        float kv = (tid<81)? (ridge-mean) : 0.f;
        s_red[tid] = fabsf(kv);
        __syncthreads();
        for(int s=128;s>0;s>>=1){ if(tid<s) s_red[tid]+=s_red[tid+s]; __syncthreads(); }
        float nrm = fmaxf(s_red[0], 1e-6f);
        if (tid<81) g_kern[i*81+tid] = kv/nrm + 0.05f*pd[i*81+tid];
    }
}

// =====================================================================
// k_conv3hp: tile 16x8, f32x2-packed 3x3 conv, shuffle stat reductions.
// 256 blocks x 256 threads.
// =====================================================================
__global__ void k_conv3hp(const float* __restrict__ w, const float* __restrict__ bias){
    __shared__ float s_in[RCn*14*22];
    __shared__ ull s_w2[72*4];          // {w(2oq), w(2oq+1)} per (ic,k), 2.25KB
    __shared__ float s_b[RCn];
    __shared__ float s_cm[12*20];
    __shared__ float s_dr[12*20];
    __shared__ float s_hp[10*18];
    __shared__ float s_r5[4*5];
    int tid = threadIdx.x;              // 256
    int blk = blockIdx.x;               // 256
    int b = blk >> 5;
    int t5 = blk & 31, ty = t5 >> 2, tx = t5 & 3;
    for(int idx=tid; idx<288; idx+=256){
        int oq = idx & 3, t = idx >> 2;           // t = ic*9+k
        s_w2[idx] = pk2(w[(2*oq)*72 + t], w[(2*oq+1)*72 + t]);
    }
    if (tid < RCn) s_b[tid]=bias[tid];
    for(int idx=tid; idx<RCn*308; idx+=256){
        int ch = idx/308, rem = idx%308;
        int r = rem/22, c = rem%22;
        int gy = ty*8 + r - 3, gx = tx*16 + c - 3;
        float v = 0.f;
        if ((unsigned)gy<64u && (unsigned)gx<64u)
            v = g_c1[((b*RCn+ch)<<12) + (gy<<6) + gx];
        s_in[ch*308 + r*22 + c] = v;
    }
    __syncthreads();
    for(int i=tid; i<240; i+=256){
        int oy=i/20, ox=i%20;
        int gy=ty*8+oy-2, gx=tx*16+ox-2;
        float sum=0.f, asum=0.f;
        if((unsigned)gy<64u && (unsigned)gx<64u){
            ull acc2[4];
            #pragma unroll
            for(int oq=0;oq<4;oq++) acc2[oq] = pk2(s_b[2*oq], s_b[2*oq+1]);
            #pragma unroll
            for(int ic=0;ic<RCn;ic++){
                const ull* wq = &s_w2[ic*36];
                const float* ip = &s_in[ic*308 + oy*22 + ox];
                #pragma unroll
                for(int dy=0;dy<3;dy++)
                    #pragma unroll
                    for(int dx=0;dx<3;dx++){
                        float in = ip[dy*22+dx];
                        ull a = pk2(in,in);
                        int kk = (dy*3+dx)*4;
                        fma2(acc2[0], a, wq[kk]);
                        fma2(acc2[1], a, wq[kk+1]);
                        fma2(acc2[2], a, wq[kk+2]);
                        fma2(acc2[3], a, wq[kk+3]);
                    }
            }
            float outv[RCn];
            #pragma unroll
            for(int oq=0;oq<4;oq++){
                float v0,v1; up2(acc2[oq],v0,v1);
                float g0 = geluf(v0), g1 = geluf(v1);
                outv[2*oq]=g0; outv[2*oq+1]=g1;
                sum += g0+g1; asum += fabsf(g0)+fabsf(g1);
            }
            if (oy>=2 && oy<10 && ox>=2 && ox<18){
                int pix = (gy<<6)+gx;
                #pragma unroll
                for(int o=0;o<RCn;o++) g_carrier[((b*RCn+o)<<12)+pix] = outv[o];
                g_densraw[(b<<12)+pix] = asum*0.125f;
            }
        }
        s_cm[i] = sum*0.125f;
        s_dr[i] = asum*0.125f;
    }
    __syncthreads();
    for(int i=tid;i<180;i+=256){
        int hy=i/18, hx=i%18;
        int gy=ty*8+hy-1, gx=tx*16+hx-1;
        float hp=0.f;
        if((unsigned)gy<64u && (unsigned)gx<64u){
            int r=hy+1, c=hx+1;
            float s=0.f;
            #pragma unroll
            for(int dy=-1;dy<=1;dy++)
                #pragma unroll
                for(int dx=-1;dx<=1;dx++)
                    s += s_cm[(r+dy)*20 + c+dx];
            hp = s_cm[r*20+c] - s/9.0f;
            if (hy>=1 && hy<9 && hx>=1 && hx<17)
                g_hp[(b<<12)+(gy<<6)+gx] = hp;
        }
        s_hp[i]=hp;
    }
    __syncthreads();
    if (tid < 128){
        int ly = (tid>>4) & 7, lx = tid&15;
        float s=0.f;
        #pragma unroll
        for(int dy=0;dy<3;dy++)
            #pragma unroll
            for(int dx=0;dx<3;dx++)
                s += fabsf(s_hp[(ly+dy)*18 + lx+dx]);
        float a = s/9.0f;
        int gi = (b<<12) + ((ty*8+ly)<<6) + tx*16+lx;
        g_asup[gi]=a;
        float d = s_dr[(ly+2)*20 + lx+2];
        float mnA=a, mxA=a, mnD=d, mxD=d, sD=d;
        #pragma unroll
        for(int off=16;off;off>>=1){
            mnA=fminf(mnA,__shfl_down_sync(0xffffffffu,mnA,off));
            mxA=fmaxf(mxA,__shfl_down_sync(0xffffffffu,mxA,off));
            mnD=fminf(mnD,__shfl_down_sync(0xffffffffu,mnD,off));
            mxD=fmaxf(mxD,__shfl_down_sync(0xffffffffu,mxD,off));
            sD +=      __shfl_down_sync(0xffffffffu,sD ,off);
        }
        int wid=tid>>5, lane=tid&31;
        if(lane==0){
            s_r5[wid*5+0]=mnA; s_r5[wid*5+1]=mxA;
            s_r5[wid*5+2]=mnD; s_r5[wid*5+3]=mxD; s_r5[wid*5+4]=sD;
        }
    }
    __syncthreads();
    if(tid==0){
        float mnA=s_r5[0], mxA=s_r5[1], mnD=s_r5[2], mxD=s_r5[3], sD=s_r5[4];
        #pragma unroll
        for(int q=1;q<4;q++){
            mnA=fminf(mnA,s_r5[q*5+0]); mxA=fmaxf(mxA,s_r5[q*5+1]);
            mnD=fminf(mnD,s_r5[q*5+2]); mxD=fmaxf(mxD,s_r5[q*5+3]); sD+=s_r5[q*5+4];
        }
        float* p = &g_part[(b*32 + t5)*5];
        p[0]=mnA; p[1]=mxA; p[2]=mnD; p[3]=mxD; p[4]=sD;
    }
}

// =====================================================================
// k_rg: tile 16x8, f32x2-packed 9x9 bank conv + gating + morphology
// + pm1+gelu -> g_h. 256 blocks x 256 threads.
// =====================================================================
__global__ void k_rg(const float* __restrict__ theta, const float* __restrict__ length,
                     const float* __restrict__ width, const float* __restrict__ plog,
                     const float* __restrict__ objn, const float* __restrict__ alpha,
                     const float* __restrict__ curv,
                     const float* __restrict__ pm1w, const float* __restrict__ pm1b){
    __shared__ ull s_k2[81*4];      // {k(2pq), k(2pq+1)} per tap, 2.5KB
    __shared__ float s_hp[18*26];
    __shared__ float s_mask[20*28];
    __shared__ float s_g0[20*28];
    __shared__ float s_er[16*24];
    __shared__ float s_ss[10*18];
    __shared__ float s_ob[10*18];
    __shared__ float s_st[5];
    __shared__ float s_p1[RCn*12];
    __shared__ float s_b1[RCn];
    int tid=threadIdx.x;                // 256
    int blk=blockIdx.x;                 // 256
    int b = blk>>5, t5 = blk&31, ty = t5>>2, tx = t5&3;
    for(int i=tid;i<324;i+=256){
        int pq = i & 3, off = i >> 2;
        s_k2[i] = pk2(g_kern[(2*pq)*81+off], g_kern[(2*pq+1)*81+off]);
    }
    if(tid<RCn*12) s_p1[tid]=pm1w[tid];
    if(tid<RCn) s_b1[tid]=pm1b[tid];
    if(tid==0){
        float mnA=1e30f,mxA=-1e30f,mnD=1e30f,mxD=-1e30f,sD=0.f;
        for(int t=0;t<32;t++){
            const float* p=&g_part[(b*32+t)*5];
            mnA=fminf(mnA,p[0]); mxA=fmaxf(mxA,p[1]);
            mnD=fminf(mnD,p[2]); mxD=fmaxf(mxD,p[3]); sD+=p[4];
        }
        s_st[0]=mnA; s_st[1]=mxA; s_st[2]=mnD; s_st[3]=mxD; s_st[4]=sD/(float)HW;
    }
    for(int i=tid;i<468;i+=256){
        int r=i/26,c=i%26;
        int gy=ty*8+r-5, gx=tx*16+c-5;
        float v=0.f;
        if((unsigned)gy<64u && (unsigned)gx<64u) v=g_hp[(b<<12)+(gy<<6)+gx];
        s_hp[i]=v;
    }
    __syncthreads();
    float mnA=s_st[0],mxA=s_st[1],mnD=s_st[2],mxD=s_st[3],meanD=s_st[4];
    float mC = fmaxf(meanD,1e-6f);
    float dmn = mnD/mC, dmx = mxD/mC;
    float invA = 1.0f/fmaxf(mxA-mnA,1e-6f);
    float invD = 1.0f/fmaxf(dmx-dmn,1e-6f);
    for(int i=tid;i<560;i+=256){
        int r=i/28,c=i%28;
        int gy=ty*8+r-6, gx=tx*16+c-6;
        float mv=1.0f, g0=0.0f;
        if((unsigned)gy<64u && (unsigned)gx<64u){
            int gi=(b<<12)+(gy<<6)+gx;
            float csup = (g_asup[gi]-mnA)*invA;
            float dsup = (g_densraw[gi]/mC - dmn)*invD;
            float ev = 0.65f*csup + 0.35f*dsup;
            mv = (ev>=0.2f)?1.0f:0.0f;
            g0 = sigmf((ev-0.2f)*12.5f);
        }
        s_mask[i]=mv; s_g0[i]=g0;
    }
    const float COSO[8]={1.0f,0.70710678f,0.0f,-0.70710678f,-1.0f,-0.70710678f,0.0f,0.70710678f};
    const float SINO[8]={0.0f,0.70710678f,1.0f,0.70710678f,0.0f,-0.70710678f,-1.0f,-0.70710678f};
    const float LA[8]={0.45f,0.75f,1.05f,0.45f,0.75f,1.05f,0.45f,0.75f};
    const float WA[8]={0.14f,0.14f,0.14f,0.2f,0.2f,0.2f,0.28f,0.28f};
    __syncthreads();
    for(int i=tid;i<180;i+=256){
        int sy=i/18, sx=i%18;
        int gy=ty*8+sy-1, gx=tx*16+sx-1;
        float ssv=0.f, ov=0.f;
        if((unsigned)gy<64u && (unsigned)gx<64u){
            int gi=(b<<12)+(gy<<6)+gx;
            ull r2[4]={0ULL,0ULL,0ULL,0ULL};
            #pragma unroll
            for(int dy=0;dy<9;dy++){
                #pragma unroll
                for(int dx=0;dx<9;dx++){
                    float hv = s_hp[(sy+dy)*26 + sx+dx];
                    ull a = pk2(hv,hv);
                    const ull* kq = &s_k2[(dy*9+dx)*4];
                    fma2(r2[0], a, kq[0]);
                    fma2(r2[1], a, kq[1]);
                    fma2(r2[2], a, kq[2]);
                    fma2(r2[3], a, kq[3]);
                }
            }
            float resp[Pp];
            #pragma unroll
            for(int pq=0;pq<4;pq++) up2(r2[pq], resp[2*pq], resp[2*pq+1]);
            float th = tanhf(theta[gi])*3.14159265358979f;
            float sth, cth; sincosf(th,&sth,&cth);
            float lv = sigmf(length[gi])*0.85f + 0.25f;
            float wv = sigmf(width[gi]) *0.22f + 0.08f;
            float bias[8];
            #pragma unroll
            for(int p=0;p<8;p++){
                float ts = cth*COSO[p] + sth*SINO[p];
                float dl = lv - LA[p];
                float dw = wv - WA[p];
                bias[p] = plog[((b*8+p)<<12) + (gy<<6)+gx] + 1.25f*ts - dl*dl*12.5f - dw*dw*100.0f;
            }
            int i1=0; float b1=bias[0];
            #pragma unroll
            for(int p=1;p<8;p++) if(bias[p]>b1){b1=bias[p];i1=p;}
            int i2=-1; float b2=-1e30f;
            #pragma unroll
            for(int p=0;p<8;p++){ if(p==i1) continue; if(bias[p]>b2){b2=bias[p];i2=p;} }
            float e = expf(b2-b1);
            float w1 = 1.0f/(1.0f+e);
            float w2 = e/(1.0f+e);
            #pragma unroll
            for(int p=0;p<8;p++){
                float wp = (p==i1)?w1:((p==i2)?w2:0.f);
                ssv = fmaf(wp, resp[p], ssv);
            }
            ov = sigmf(objn[gi]);
        }
        s_ss[i]=ssv; s_ob[i]=ov;
    }
    __syncthreads();
    for(int i=tid;i<384;i+=256){
        int ey=i/24, ex=i%24;
        int gy=ty*8+ey-4, gx=tx*16+ex-4;
        float m=0.f;
        if((unsigned)gy<64u && (unsigned)gx<64u){
            m=1.0f;
            #pragma unroll
            for(int dy=0;dy<5;dy++)
                #pragma unroll
                for(int dx=0;dx<5;dx++)
                    m=fminf(m, s_mask[(ey+dy)*28 + ex+dx]);
        }
        s_er[i]=m;
    }
    __syncthreads();
    if (tid < 128){
        int ly=(tid>>4)&7, lx=tid&15;
        float m9=0.f;
        #pragma unroll
        for(int dy=0;dy<9;dy++)
            #pragma unroll
            for(int dx=0;dx<9;dx++)
                m9=fmaxf(m9, s_er[(ly+dy)*24 + lx+dx]);
        float g5=0.f;
        #pragma unroll
        for(int dy=0;dy<5;dy++)
            #pragma unroll
            for(int dx=0;dx<5;dx++)
                g5=fmaxf(g5, s_g0[(ly+4+dy)*28 + lx+4+dx]);
        float gate = g5*m9;
        float so=0.f, sv=0.f;
        #pragma unroll
        for(int dy=0;dy<3;dy++)
            #pragma unroll
            for(int dx=0;dx<3;dx++){
                so += s_ob[(ly+dy)*18 + lx+dx];
                sv += s_ss[(ly+dy)*18 + lx+dx];
            }
        float blob = (so/9.0f)*gate;
        float ss2 = s_ss[(ly+1)*18 + lx+1] - sv/9.0f;
        int gi = (b<<12) + ((ty*8+ly)<<6) + tx*16+lx;
        float d = g_densraw[gi]/mC;
        float cv = tanhf(curv[gi]);
        float sg = sigmf(alpha[gi])*blob*(0.7f + 0.3f*fminf(fmaxf(d,0.f),2.0f));
        float ssf = sg*ss2*(1.0f + 0.15f*cv);
        float th2 = tanhf(theta[gi])*3.14159265358979f;
        float sth2, cth2; sincosf(th2,&sth2,&cth2);
        float f[12];
        #pragma unroll
        for(int o=0;o<RCn;o++) f[o] = g_carrier[((b*RCn+o)<<12) + (gi&4095)]*ssf;
        f[8]=ssf; f[9]=cth2*ssf; f[10]=sth2*ssf; f[11]=cv*ssf;
        #pragma unroll
        for(int o=0;o<RCn;o++){
            float acc = s_b1[o];
            #pragma unroll
            for(int j=0;j<12;j++) acc = fmaf(s_p1[o*12+j], f[j], acc);
            g_h[(o<<15) + gi] = geluf(acc);
        }
    }
}

// =====================================================================
// k_out: GEMV 8 -> 768, f32x2 packed, float4 stores.
// 512 blocks (32 px-blocks x 16 splits of 48) x 256 threads.
// =====================================================================
__global__ void k_out(const float* __restrict__ pm2w, const float* __restrict__ pm2b,
                      float* __restrict__ out){
    __shared__ ull s_w2[48*RCn];     // {w,w} packed, 3KB
    __shared__ float s_b[48];
    int tid = threadIdx.x;            // 256
    int pb = blockIdx.x >> 4;
    int sp = blockIdx.x & 15;
    for(int i=tid;i<48*RCn;i+=256){
        float wv = pm2w[sp*48*RCn + i];
        s_w2[i] = pk2(wv, wv);
    }
    if(tid<48) s_b[tid]=pm2b[sp*48 + tid];
    __syncthreads();
    int g4 = pb*256 + tid;
    int b = g4 >> 10;
    int pix = (g4 << 2) & 4095;
    ull h01[RCn], h23[RCn];
    #pragma unroll
    for(int k=0;k<RCn;k++){
        float4 h4 = __ldg((const float4*)&g_h[(k<<15) + (g4<<2)]);
        h01[k] = pk2(h4.x, h4.y);
        h23[k] = pk2(h4.z, h4.w);
    }
    float* op = out + ((size_t)b*FCn + sp*48)*HW + pix;
    #pragma unroll 4
    for(int o=0;o<48;o++){
        const ull* wr = &s_w2[o*RCn];
        float bo = s_b[o];
        ull a01 = pk2(bo,bo), a23 = pk2(bo,bo);
        #pragma unroll
        for(int k=0;k<RCn;k++){
            ull w2 = wr[k];
            fma2(a01, h01[k], w2);
            fma2(a23, h23[k], w2);
        }
        float4 r;
        up2(a01, r.x, r.y); up2(a23, r.z, r.w);
        *(float4*)(op + (size_t)o*HW) = r;
    }
}

extern "C" void kernel_launch(void* const* d_in, const int* in_sizes, int n_in,
                              void* d_out, int out_size){
    const float* fm     = (const float*)d_in[0];
    const float* theta  = (const float*)d_in[1];
    const float* length = (const float*)d_in[2];
    const float* width  = (const float*)d_in[3];
    const float* curv   = (const float*)d_in[4];
    const float* alpha  = (const float*)d_in[5];
    const float* objn   = (const float*)d_in[6];
    const float* plog   = (const float*)d_in[7];
    const float* fp1w   = (const float*)d_in[8];
    const float* fp1b   = (const float*)d_in[9];
    const float* fp2w   = (const float*)d_in[10];
    const float* fp2b   = (const float*)d_in[11];
    const float* pm1w   = (const float*)d_in[12];
    const float* pm1b   = (const float*)d_in[13];
    const float* pm2w   = (const float*)d_in[14];
    const float* pm2b   = (const float*)d_in[15];
    const float* pd     = (const float*)d_in[16];
    float* out = (float*)d_out;

    k_conv1  <<<512, 256>>>(fm, fp1w, fp1b, pd);
    k_conv3hp<<<256, 256>>>(fp2w, fp2b);
    k_rg     <<<256, 256>>>(theta, length, width, plog, objn, alpha, curv, pm1w, pm1b);
    k_out    <<<512, 256>>>(pm2w, pm2b, out);
}

// round 8
// speedup vs baseline: 1.1396x; 1.1396x over previous
#include <cuda_runtime.h>
#include <math.h>

#define Pp 8
#define RCn 8
#define FCn 768
#define Bb 8
#define HW 4096

// ---------------- scratch (device globals; no allocation) ----------------
__device__ float g_kern[Pp*81];
__device__ float g_c1[Bb*RCn*HW];
__device__ float g_carrier[Bb*RCn*HW];
__device__ float g_densraw[Bb*HW];
__device__ float g_hp[Bb*HW];
__device__ float g_asup[Bb*HW];
__device__ float g_part[Bb*32*5];   // per-tile partials: mnA,mxA,mnD,mxD,sumD
__device__ float g_h[RCn*Bb*HW];    // hidden after pm1+gelu, channel-major

__device__ __forceinline__ float geluf(float x){ return 0.5f*x*(1.0f+erff(x*0.70710678118654752f)); }
__device__ __forceinline__ float sigmf(float x){ return 1.0f/(1.0f+expf(-x)); }

// =====================================================================
// k_conv1: 1x1 conv 768->8 + gelu. float4 pixels, 16-way channel split.
// 512 blocks x 256 threads; block = 64 pixels (16 float4 groups).
// Blocks 0..7 additionally build the filter bank.
// =====================================================================
__global__ void k_conv1(const float* __restrict__ fm,
                        const float* __restrict__ w,
                        const float* __restrict__ bias,
                        const float* __restrict__ pd){
    __shared__ float sw[FCn*RCn];           // [c][o] 24KB
    __shared__ float4 s_part[15*16*RCn];    // partials from splits 1..15, 30KB
    __shared__ float s_red[256];
    int tid = threadIdx.x;                  // 256
    for(int idx = tid; idx < FCn*RCn; idx += 256){
        int o = idx / FCn, c = idx % FCn;
        sw[c*RCn + o] = w[idx];
    }
    __syncthreads();
    int lane = tid & 15;                    // float4 pixel group within block
    int sp   = tid >> 4;                    // channel split 0..15 (48 ch each)
    int g4 = blockIdx.x*16 + lane;          // global float4 group (0..8191)
    int b = g4 >> 10;
    int pix = (g4 << 2) & 4095;
    const float* xp = fm + ((size_t)b*FCn + sp*48)*HW + pix;
    float4 acc[RCn];
    #pragma unroll
    for(int o=0;o<RCn;o++){ acc[o].x=0.f; acc[o].y=0.f; acc[o].z=0.f; acc[o].w=0.f; }
    #pragma unroll 8
    for(int c=0;c<48;c++){
        float4 xv = __ldg((const float4*)(xp + (size_t)c*HW));
        const float* wr = &sw[(sp*48 + c)*RCn];
        #pragma unroll
        for(int o=0;o<RCn;o++){
            float wv = wr[o];
            acc[o].x = fmaf(xv.x, wv, acc[o].x);
            acc[o].y = fmaf(xv.y, wv, acc[o].y);
            acc[o].z = fmaf(xv.z, wv, acc[o].z);
            acc[o].w = fmaf(xv.w, wv, acc[o].w);
        }
    }
    if (sp > 0){
        #pragma unroll
        for(int o=0;o<RCn;o++) s_part[((sp-1)*16 + lane)*RCn + o] = acc[o];
    }
    __syncthreads();
    if (sp == 0){
        #pragma unroll
        for(int o=0;o<RCn;o++){
            float4 a = acc[o];
            #pragma unroll
            for(int q=0;q<15;q++){
                float4 p = s_part[(q*16 + lane)*RCn + o];
                a.x+=p.x; a.y+=p.y; a.z+=p.z; a.w+=p.w;
            }
            float bo = bias[o];
            float4 r;
            r.x = geluf(a.x+bo); r.y = geluf(a.y+bo);
            r.z = geluf(a.z+bo); r.w = geluf(a.w+bo);
            *(float4*)&g_c1[((b*RCn+o)<<12) + pix] = r;
        }
    }
    // ---- filter bank (blocks 0..7) ----
    if (blockIdx.x < 8){
        int i = blockIdx.x;
        float ridge = 0.f;
        if (tid < 81){
            int r = tid/9, c = tid%9;
            float y = -1.0f + 0.25f*(float)r;
            float x = -1.0f + 0.25f*(float)c;
            double angd = 6.283185307179586476925286766559 * (double)i / 8.0;
            const float Ls[3] = {0.45f,0.75f,1.05f};
            const float Ws[3] = {0.14f,0.2f,0.28f};
            float L = Ls[i%3], Wd = Ws[(i/3)%3];
            float ca = (float)cos(angd), sa = (float)sin(angd);
            float xr =  x*ca + y*sa;
            float yr = -x*sa + y*ca;
            float tpr = 1.0f - fminf(fabsf(xr)/L, 1.0f);
            tpr = tpr*sqrtf(tpr);
            float ax = xr/L, ay = yr/Wd;
            float core = expf(-0.5f*(ax*ax + ay*ay));
            float lobe = fmaxf(1.0f - ay*ay, 0.0f);
            ridge = tpr*core*lobe;
        }
        __syncthreads();
        s_red[tid] = (tid<81)? ridge : 0.f;
        __syncthreads();
        for(int s=128;s>0;s>>=1){ if(tid<s) s_red[tid]+=s_red[tid+s]; __syncthreads(); }
        float mean = s_red[0]/81.0f;
        __syncthreads();
        float kv = (tid<81)? (ridge-mean) : 0.f;
        s_red[tid] = fabsf(kv);
        __syncthreads();
        for(int s=128;s>0;s>>=1){ if(tid<s) s_red[tid]+=s_red[tid+s]; __syncthreads(); }
        float nrm = fmaxf(s_red[0], 1e-6f);
        if (tid<81) g_kern[i*81+tid] = kv/nrm + 0.05f*pd[i*81+tid];
    }
}

// =====================================================================
// k_conv3hp: tile 16x8. 3x3 conv 8->8 + gelu over halo region, carrier,
// cmean/hp/asup/densraw + per-tile stat partials. 256 blocks x 256 thr.
// =====================================================================
__global__ void k_conv3hp(const float* __restrict__ w, const float* __restrict__ bias){
    __shared__ float s_in[RCn*14*22];   // halo 3
    __shared__ float s_w[RCn*RCn*9];
    __shared__ float s_b[RCn];
    __shared__ float s_cm[12*20];
    __shared__ float s_dr[12*20];
    __shared__ float s_hp[10*18];
    __shared__ float s_red[256];
    int tid = threadIdx.x;              // 256
    int blk = blockIdx.x;               // 256 = 8 images * 32 tiles
    int b = blk >> 5;
    int t5 = blk & 31, ty = t5 >> 2, tx = t5 & 3;
    for(int idx=tid; idx<RCn*RCn*9; idx+=256) s_w[idx]=w[idx];
    if (tid < RCn) s_b[tid]=bias[tid];
    for(int idx=tid; idx<RCn*308; idx+=256){
        int ch = idx/308, rem = idx%308;
        int r = rem/22, c = rem%22;
        int gy = ty*8 + r - 3, gx = tx*16 + c - 3;
        float v = 0.f;
        if ((unsigned)gy<64u && (unsigned)gx<64u)
            v = g_c1[((b*RCn+ch)<<12) + (gy<<6) + gx];
        s_in[ch*308 + r*22 + c] = v;
    }
    __syncthreads();
    for(int i=tid; i<240; i+=256){
        int oy=i/20, ox=i%20;
        int gy=ty*8+oy-2, gx=tx*16+ox-2;
        float sum=0.f, asum=0.f;
        if((unsigned)gy<64u && (unsigned)gx<64u){
            float outv[RCn];
            #pragma unroll
            for(int o=0;o<RCn;o++){
                float acc = s_b[o];
                #pragma unroll
                for(int ic=0;ic<RCn;ic++){
                    const float* wr = &s_w[(o*RCn+ic)*9];
                    const float* ip = &s_in[ic*308 + oy*22 + ox];
                    #pragma unroll
                    for(int dy=0;dy<3;dy++)
                        #pragma unroll
                        for(int dx=0;dx<3;dx++)
                            acc = fmaf(wr[dy*3+dx], ip[dy*22+dx], acc);
                }
                float gv = geluf(acc);
                outv[o]=gv; sum+=gv; asum+=fabsf(gv);
            }
            if (oy>=2 && oy<10 && ox>=2 && ox<18){
                int pix = (gy<<6)+gx;
                #pragma unroll
                for(int o=0;o<RCn;o++) g_carrier[((b*RCn+o)<<12)+pix] = outv[o];
                g_densraw[(b<<12)+pix] = asum*0.125f;
            }
        }
        s_cm[i] = sum*0.125f;
        s_dr[i] = asum*0.125f;
    }
    __syncthreads();
    for(int i=tid;i<180;i+=256){
        int hy=i/18, hx=i%18;
        int gy=ty*8+hy-1, gx=tx*16+hx-1;
        float hp=0.f;
        if((unsigned)gy<64u && (unsigned)gx<64u){
            int r=hy+1, c=hx+1;
            float s=0.f;
            #pragma unroll
            for(int dy=-1;dy<=1;dy++)
                #pragma unroll
                for(int dx=-1;dx<=1;dx++)
                    s += s_cm[(r+dy)*20 + c+dx];
            hp = s_cm[r*20+c] - s/9.0f;
            if (hy>=1 && hy<9 && hx>=1 && hx<17)
                g_hp[(b<<12)+(gy<<6)+gx] = hp;
        }
        s_hp[i]=hp;
    }
    __syncthreads();
    bool act = tid < 128;
    int ly = (tid>>4) & 7, lx = tid&15;
    float a=0.f, d=0.f;
    if (act){
        float s=0.f;
        #pragma unroll
        for(int dy=0;dy<3;dy++)
            #pragma unroll
            for(int dx=0;dx<3;dx++)
                s += fabsf(s_hp[(ly+dy)*18 + lx+dx]);
        a = s/9.0f;
        int gi = (b<<12) + ((ty*8+ly)<<6) + tx*16+lx;
        g_asup[gi]=a;
        d = s_dr[(ly+2)*20 + lx+2];
    }
    s_red[tid]= act? a : 1e30f; __syncthreads();
    for(int s2=128;s2>0;s2>>=1){ if(tid<s2) s_red[tid]=fminf(s_red[tid],s_red[tid+s2]); __syncthreads(); }
    float mnA=s_red[0]; __syncthreads();
    s_red[tid]= act? a : -1e30f; __syncthreads();
    for(int s2=128;s2>0;s2>>=1){ if(tid<s2) s_red[tid]=fmaxf(s_red[tid],s_red[tid+s2]); __syncthreads(); }
    float mxA=s_red[0]; __syncthreads();
    s_red[tid]= act? d : 1e30f; __syncthreads();
    for(int s2=128;s2>0;s2>>=1){ if(tid<s2) s_red[tid]=fminf(s_red[tid],s_red[tid+s2]); __syncthreads(); }
    float mnD=s_red[0]; __syncthreads();
    s_red[tid]= act? d : -1e30f; __syncthreads();
    for(int s2=128;s2>0;s2>>=1){ if(tid<s2) s_red[tid]=fmaxf(s_red[tid],s_red[tid+s2]); __syncthreads(); }
    float mxD=s_red[0]; __syncthreads();
    s_red[tid]= act? d : 0.f; __syncthreads();
    for(int s2=128;s2>0;s2>>=1){ if(tid<s2) s_red[tid]+=s_red[tid+s2]; __syncthreads(); }
    if(tid==0){
        float* p = &g_part[(b*32 + t5)*5];
        p[0]=mnA; p[1]=mxA; p[2]=mnD; p[3]=mxD; p[4]=s_red[0];
    }
}

// =====================================================================
// k_rg: tile 16x8. 9x9 bank conv + softmax-top2 + gating + morphology
// + final ss + pm1+gelu -> g_h. 256 blocks x 256 threads.
// =====================================================================
__global__ void k_rg(const float* __restrict__ theta, const float* __restrict__ length,
                     const float* __restrict__ width, const float* __restrict__ plog,
                     const float* __restrict__ objn, const float* __restrict__ alpha,
                     const float* __restrict__ curv,
                     const float* __restrict__ pm1w, const float* __restrict__ pm1b){
    __shared__ float s_k[Pp*81];
    __shared__ float s_hp[18*26];
    __shared__ float s_mask[20*28];
    __shared__ float s_g0[20*28];
    __shared__ float s_er[16*24];
    __shared__ float s_ss[10*18];
    __shared__ float s_ob[10*18];
    __shared__ float s_st[5];
    __shared__ float s_p1[RCn*12];
    __shared__ float s_b1[RCn];
    int tid=threadIdx.x;                // 256
    int blk=blockIdx.x;                 // 256
    int b = blk>>5, t5 = blk&31, ty = t5>>2, tx = t5&3;
    for(int i=tid;i<Pp*81;i+=256) s_k[i]=g_kern[i];
    if(tid<RCn*12) s_p1[tid]=pm1w[tid];
    if(tid<RCn) s_b1[tid]=pm1b[tid];
    if(tid==0){
        float mnA=1e30f,mxA=-1e30f,mnD=1e30f,mxD=-1e30f,sD=0.f;
        for(int t=0;t<32;t++){
            const float* p=&g_part[(b*32+t)*5];
            mnA=fminf(mnA,p[0]); mxA=fmaxf(mxA,p[1]);
            mnD=fminf(mnD,p[2]); mxD=fmaxf(mxD,p[3]); sD+=p[4];
        }
        s_st[0]=mnA; s_st[1]=mxA; s_st[2]=mnD; s_st[3]=mxD; s_st[4]=sD/(float)HW;
    }
    for(int i=tid;i<468;i+=256){
        int r=i/26,c=i%26;
        int gy=ty*8+r-5, gx=tx*16+c-5;
        float v=0.f;
        if((unsigned)gy<64u && (unsigned)gx<64u) v=g_hp[(b<<12)+(gy<<6)+gx];
        s_hp[i]=v;
    }
    __syncthreads();
    float mnA=s_st[0],mxA=s_st[1],mnD=s_st[2],mxD=s_st[3],meanD=s_st[4];
    float mC = fmaxf(meanD,1e-6f);
    float dmn = mnD/mC, dmx = mxD/mC;
    float invA = 1.0f/fmaxf(mxA-mnA,1e-6f);
    float invD = 1.0f/fmaxf(dmx-dmn,1e-6f);
    for(int i=tid;i<560;i+=256){
        int r=i/28,c=i%28;
        int gy=ty*8+r-6, gx=tx*16+c-6;
        float mv=1.0f, g0=0.0f;
        if((unsigned)gy<64u && (unsigned)gx<64u){
            int gi=(b<<12)+(gy<<6)+gx;
            float csup = (g_asup[gi]-mnA)*invA;
            float dsup = (g_densraw[gi]/mC - dmn)*invD;
            float ev = 0.65f*csup + 0.35f*dsup;
            mv = (ev>=0.2f)?1.0f:0.0f;
            g0 = sigmf((ev-0.2f)*12.5f);
        }
        s_mask[i]=mv; s_g0[i]=g0;
    }
    const float COSO[8]={1.0f,0.70710678f,0.0f,-0.70710678f,-1.0f,-0.70710678f,0.0f,0.70710678f};
    const float SINO[8]={0.0f,0.70710678f,1.0f,0.70710678f,0.0f,-0.70710678f,-1.0f,-0.70710678f};
    const float LA[8]={0.45f,0.75f,1.05f,0.45f,0.75f,1.05f,0.45f,0.75f};
    const float WA[8]={0.14f,0.14f,0.14f,0.2f,0.2f,0.2f,0.28f,0.28f};
    __syncthreads();
    for(int i=tid;i<180;i+=256){
        int sy=i/18, sx=i%18;
        int gy=ty*8+sy-1, gx=tx*16+sx-1;
        float ssv=0.f, ov=0.f;
        if((unsigned)gy<64u && (unsigned)gx<64u){
            int gi=(b<<12)+(gy<<6)+gx;
            float resp[Pp];
            #pragma unroll
            for(int p=0;p<Pp;p++) resp[p]=0.f;
            #pragma unroll
            for(int dy=0;dy<9;dy++){
                #pragma unroll
                for(int dx=0;dx<9;dx++){
                    float hv = s_hp[(sy+dy)*26 + sx+dx];
                    int off = dy*9+dx;
                    #pragma unroll
                    for(int p=0;p<Pp;p++) resp[p]=fmaf(s_k[p*81+off],hv,resp[p]);
                }
            }
            float th = tanhf(theta[gi])*3.14159265358979f;
            float sth, cth; sincosf(th,&sth,&cth);
            float lv = sigmf(length[gi])*0.85f + 0.25f;
            float wv = sigmf(width[gi]) *0.22f + 0.08f;
            float bias[8];
            #pragma unroll
            for(int p=0;p<8;p++){
                float ts = cth*COSO[p] + sth*SINO[p];
                float dl = lv - LA[p];
                float dw = wv - WA[p];
                bias[p] = plog[((b*8+p)<<12) + (gy<<6)+gx] + 1.25f*ts - dl*dl*12.5f - dw*dw*100.0f;
            }
            int i1=0; float b1=bias[0];
            #pragma unroll
            for(int p=1;p<8;p++) if(bias[p]>b1){b1=bias[p];i1=p;}
            int i2=-1; float b2=-1e30f;
            #pragma unroll
            for(int p=0;p<8;p++){ if(p==i1) continue; if(bias[p]>b2){b2=bias[p];i2=p;} }
            float e = expf(b2-b1);
            float w1 = 1.0f/(1.0f+e);
            float w2 = e/(1.0f+e);
            #pragma unroll
            for(int p=0;p<8;p++){
                float wp = (p==i1)?w1:((p==i2)?w2:0.f);
                ssv = fmaf(wp, resp[p], ssv);
            }
            ov = sigmf(objn[gi]);
        }
        s_ss[i]=ssv; s_ob[i]=ov;
    }
    __syncthreads();
    for(int i=tid;i<384;i+=256){
        int ey=i/24, ex=i%24;
        int gy=ty*8+ey-4, gx=tx*16+ex-4;
        float m=0.f;
        if((unsigned)gy<64u && (unsigned)gx<64u){
            m=1.0f;
            #pragma unroll
            for(int dy=0;dy<5;dy++)
                #pragma unroll
                for(int dx=0;dx<5;dx++)
                    m=fminf(m, s_mask[(ey+dy)*28 + ex+dx]);
        }
        s_er[i]=m;
    }
    __syncthreads();
    if (tid < 128){
        int ly=(tid>>4)&7, lx=tid&15;
        float m9=0.f;
        #pragma unroll
        for(int dy=0;dy<9;dy++)
            #pragma unroll
            for(int dx=0;dx<9;dx++)
                m9=fmaxf(m9, s_er[(ly+dy)*24 + lx+dx]);
        float g5=0.f;
        #pragma unroll
        for(int dy=0;dy<5;dy++)
            #pragma unroll
            for(int dx=0;dx<5;dx++)
                g5=fmaxf(g5, s_g0[(ly+4+dy)*28 + lx+4+dx]);
        float gate = g5*m9;
        float so=0.f, sv=0.f;
        #pragma unroll
        for(int dy=0;dy<3;dy++)
            #pragma unroll
            for(int dx=0;dx<3;dx++){
                so += s_ob[(ly+dy)*18 + lx+dx];
                sv += s_ss[(ly+dy)*18 + lx+dx];
            }
        float blob = (so/9.0f)*gate;
        float ss2 = s_ss[(ly+1)*18 + lx+1] - sv/9.0f;
        int gi = (b<<12) + ((ty*8+ly)<<6) + tx*16+lx;
        float d = g_densraw[gi]/mC;
        float cv = tanhf(curv[gi]);
        float sg = sigmf(alpha[gi])*blob*(0.7f + 0.3f*fminf(fmaxf(d,0.f),2.0f));
        float ssf = sg*ss2*(1.0f + 0.15f*cv);
        float th2 = tanhf(theta[gi])*3.14159265358979f;
        float sth2, cth2; sincosf(th2,&sth2,&cth2);
        float f[12];
        #pragma unroll
        for(int o=0;o<RCn;o++) f[o] = g_carrier[((b*RCn+o)<<12) + (gi&4095)]*ssf;
        f[8]=ssf; f[9]=cth2*ssf; f[10]=sth2*ssf; f[11]=cv*ssf;
        #pragma unroll
        for(int o=0;o<RCn;o++){
            float acc = s_b1[o];
            #pragma unroll
            for(int j=0;j<12;j++) acc = fmaf(s_p1[o*12+j], f[j], acc);
            g_h[(o<<15) + gi] = geluf(acc);
        }
    }
}

// =====================================================================
// k_out: pure GEMV 8 -> 768, float4 pixels + float4 stores.
// 1024 blocks (64 pixel-blocks x 16 channel splits of 48) x 128 threads.
// =====================================================================
__global__ void __launch_bounds__(128) k_out(const float* __restrict__ pm2w,
                      const float* __restrict__ pm2b,
                      float* __restrict__ out){
    __shared__ float s_w[48*RCn];
    __shared__ float s_b[48];
    int tid = threadIdx.x;            // 128
    int pb = blockIdx.x >> 4;         // pixel block 0..63
    int sp = blockIdx.x & 15;         // channel split 0..15 (48 out ch)
    for(int i=tid;i<48*RCn;i+=128) s_w[i]=pm2w[sp*48*RCn + i];
    if(tid<48) s_b[tid]=pm2b[sp*48 + tid];
    __syncthreads();
    int g4 = pb*128 + tid;            // float4 pixel group, 0..8191
    int b = g4 >> 10;
    int pix = (g4 << 2) & 4095;
    float4 h4[RCn];
    #pragma unroll
    for(int k=0;k<RCn;k++) h4[k] = __ldg((const float4*)&g_h[(k<<15) + (g4<<2)]);
    float* op = out + ((size_t)b*FCn + sp*48)*HW + pix;
    #pragma unroll
    for(int o=0;o<48;o++){
        const float* wr = &s_w[o*RCn];
        float bo = s_b[o];
        float4 a; a.x=bo; a.y=bo; a.z=bo; a.w=bo;
        #pragma unroll
        for(int k=0;k<RCn;k++){
            float wv = wr[k];
            a.x = fmaf(wv, h4[k].x, a.x);
            a.y = fmaf(wv, h4[k].y, a.y);
            a.z = fmaf(wv, h4[k].z, a.z);
            a.w = fmaf(wv, h4[k].w, a.w);
        }
        *(float4*)(op + (size_t)o*HW) = a;
    }
}

extern "C" void kernel_launch(void* const* d_in, const int* in_sizes, int n_in,
                              void* d_out, int out_size){
    const float* fm     = (const float*)d_in[0];
    const float* theta  = (const float*)d_in[1];
    const float* length = (const float*)d_in[2];
    const float* width  = (const float*)d_in[3];
    const float* curv   = (const float*)d_in[4];
    const float* alpha  = (const float*)d_in[5];
    const float* objn   = (const float*)d_in[6];
    const float* plog   = (const float*)d_in[7];
    const float* fp1w   = (const float*)d_in[8];
    const float* fp1b   = (const float*)d_in[9];
    const float* fp2w   = (const float*)d_in[10];
    const float* fp2b   = (const float*)d_in[11];
    const float* pm1w   = (const float*)d_in[12];
    const float* pm1b   = (const float*)d_in[13];
    const float* pm2w   = (const float*)d_in[14];
    const float* pm2b   = (const float*)d_in[15];
    const float* pd     = (const float*)d_in[16];
    float* out = (float*)d_out;

    k_conv1  <<<512, 256>>>(fm, fp1w, fp1b, pd);
    k_conv3hp<<<256, 256>>>(fp2w, fp2b);
    k_rg     <<<256, 256>>>(theta, length, width, plog, objn, alpha, curv, pm1w, pm1b);
    k_out    <<<1024, 128>>>(pm2w, pm2b, out);
}